// round 13
// baseline (speedup 1.0000x reference)
#include <cuda_runtime.h>
#include <cuda_bf16.h>
#include <stdint.h>

#define DIMS     128
#define MSLOTS   64
#define TILE_R   128
#define NTH      128
#define NSM      148

// ---------------- SMEM layout (byte offsets), per CTA ----------------
// xh/xm: [128 rows][128 bf16], 256B pitch, 16B-unit xor swizzle (col16 ^= row&7)
#define XH      0u
#define XM      32768u
// B1 (mem + gate row, k128 x n72): [72 slots][272B pitch] bf16
// pitch 272 = 17*16B (odd multiple of 16B -> conflict-free ldmatrix row gather)
#define B1Hoff  65536u
#define B1Moff  85120u
#define B1_PITCH 272
#define SMEM_TOTAL 104704u

static __device__ __forceinline__ uint32_t smem_u32(const void* p) {
    uint32_t a;
    asm("{ .reg .u64 t; cvta.to.shared.u64 t, %1; cvt.u32.u64 %0, t; }" : "=r"(a) : "l"(p));
    return a;
}
static __device__ __forceinline__ void ldsm4(uint32_t* r, uint32_t a) {
    asm volatile("ldmatrix.sync.aligned.m8n8.x4.shared.b16 {%0,%1,%2,%3}, [%4];"
                 : "=r"(r[0]), "=r"(r[1]), "=r"(r[2]), "=r"(r[3]) : "r"(a));
}
static __device__ __forceinline__ void ldsm4t(uint32_t* r, uint32_t a) {
    asm volatile("ldmatrix.sync.aligned.m8n8.x4.trans.shared.b16 {%0,%1,%2,%3}, [%4];"
                 : "=r"(r[0]), "=r"(r[1]), "=r"(r[2]), "=r"(r[3]) : "r"(a));
}
static __device__ __forceinline__ void mma16816(float* d, const uint32_t* a,
                                                uint32_t b0, uint32_t b1) {
    asm volatile(
        "mma.sync.aligned.m16n8k16.row.col.f32.bf16.bf16.f32 "
        "{%0,%1,%2,%3}, {%4,%5,%6,%7}, {%8,%9}, {%0,%1,%2,%3};"
        : "+f"(d[0]), "+f"(d[1]), "+f"(d[2]), "+f"(d[3])
        : "r"(a[0]), "r"(a[1]), "r"(a[2]), "r"(a[3]), "r"(b0), "r"(b1));
}
static __device__ __forceinline__ uint32_t pk2bf(__nv_bfloat16 a, __nv_bfloat16 b) {
    __nv_bfloat162 t; t.x = a; t.y = b;
    return *reinterpret_cast<uint32_t*>(&t);
}
static __device__ __forceinline__ void splitpk(float a, float b,
                                               uint32_t& hi, uint32_t& mid) {
    __nv_bfloat16 ha = __float2bfloat16_rn(a);
    __nv_bfloat16 hb = __float2bfloat16_rn(b);
    hi  = pk2bf(ha, hb);
    mid = pk2bf(__float2bfloat16_rn(a - __bfloat162float(ha)),
                __float2bfloat16_rn(b - __bfloat162float(hb)));
}
static __device__ __forceinline__ float2 ubf2(uint32_t v) {
    return __bfloat1622float2(*reinterpret_cast<__nv_bfloat162*>(&v));
}

__global__ void __launch_bounds__(NTH, 2)
gated_memory_mma(const float* __restrict__ x,
                 const float* __restrict__ mem,
                 const float* __restrict__ gate_w,
                 const float* __restrict__ gate_b,
                 float* __restrict__ out,
                 int n, int ntiles)
{
    extern __shared__ char smc[];
    const uint32_t sb = smem_u32(smc);
    const int tid  = threadIdx.x;
    const int lane = tid & 31;
    const int w    = tid >> 5;          // warp 0..3; rows w*32..w*32+31
    const int q    = lane & 3;
    const int gp   = lane >> 2;

    // ---- stage B1 (mem rows + gate row + zero pad), hi/mid split ----
    for (int i = tid; i < MSLOTS * DIMS; i += NTH) {
        int s = i >> 7, d = i & 127;
        float v = mem[i];
        __nv_bfloat16 h = __float2bfloat16_rn(v);
        __nv_bfloat16 m = __float2bfloat16_rn(v - __bfloat162float(h));
        *(__nv_bfloat16*)(smc + B1Hoff + s * B1_PITCH + d * 2) = h;
        *(__nv_bfloat16*)(smc + B1Moff + s * B1_PITCH + d * 2) = m;
    }
    if (tid < DIMS) {   // gate row = slot 64
        float v = gate_w[tid];
        __nv_bfloat16 h = __float2bfloat16_rn(v);
        __nv_bfloat16 m = __float2bfloat16_rn(v - __bfloat162float(h));
        *(__nv_bfloat16*)(smc + B1Hoff + 64 * B1_PITCH + tid * 2) = h;
        *(__nv_bfloat16*)(smc + B1Moff + 64 * B1_PITCH + tid * 2) = m;
    }
    for (int i = tid; i < 476; i += NTH) {   // zero slots 65..71
        *(uint32_t*)(smc + B1Hoff + 65 * B1_PITCH + i * 4) = 0u;
        *(uint32_t*)(smc + B1Moff + 65 * B1_PITCH + i * 4) = 0u;
    }
    const float gbias = gate_b[0];

    const float4* xg = reinterpret_cast<const float4*>(x);

    for (int t = blockIdx.x; t < ntiles; t += gridDim.x) {
        const int row0 = t * TILE_R;

        // ---- stage x tile: split fp32 -> bf16 hi/mid, swizzled 16B stores ----
        #pragma unroll
        for (int it = 0; it < 16; ++it) {
            int lin = it * NTH + tid;
            int row = lin >> 4, c16 = lin & 15;
            float4 v0 = make_float4(0.f, 0.f, 0.f, 0.f), v1 = v0;
            int g = row0 + row;
            if (g < n) {
                v0 = xg[(size_t)g * 32 + c16 * 2];
                v1 = xg[(size_t)g * 32 + c16 * 2 + 1];
            }
            uint4 H, M;
            splitpk(v0.x, v0.y, H.x, M.x);
            splitpk(v0.z, v0.w, H.y, M.y);
            splitpk(v1.x, v1.y, H.z, M.z);
            splitpk(v1.z, v1.w, H.w, M.w);
            uint32_t off = row * 256 + ((c16 ^ (row & 7)) << 4);
            *reinterpret_cast<uint4*>(smc + XH + off) = H;
            *reinterpret_cast<uint4*>(smc + XM + off) = M;
        }
        __syncthreads();

        // ---- GEMM1: sim[32 x 72] per warp = x @ [mem|gw]^T, 3-pass split ----
        float acc[2][9][4];
        #pragma unroll
        for (int mt = 0; mt < 2; ++mt)
            #pragma unroll
            for (int nt = 0; nt < 9; ++nt)
                #pragma unroll
                for (int j = 0; j < 4; ++j) acc[mt][nt][j] = 0.f;

        const int lr = lane & 7, mi = lane >> 3;
        #pragma unroll
        for (int kt = 0; kt < 8; ++kt) {
            uint32_t ah[2][4], am[2][4];
            #pragma unroll
            for (int mt = 0; mt < 2; ++mt) {
                int row = w * 32 + mt * 16 + (mi & 1) * 8 + lr;
                int c16 = 2 * kt + (mi >> 1);
                uint32_t off = row * 256 + ((c16 ^ (row & 7)) << 4);
                ldsm4(ah[mt], sb + XH + off);
                ldsm4(am[mt], sb + XM + off);
            }
            #pragma unroll
            for (int nt = 0; nt < 9; ++nt) {
                uint32_t bo = B1Hoff + (nt * 8 + gp) * B1_PITCH + (kt * 16 + 2 * q) * 2;
                uint32_t bh0 = *(const uint32_t*)(smc + bo);
                uint32_t bh1 = *(const uint32_t*)(smc + bo + 16);
                uint32_t bm0 = *(const uint32_t*)(smc + bo + (B1Moff - B1Hoff));
                uint32_t bm1 = *(const uint32_t*)(smc + bo + (B1Moff - B1Hoff) + 16);
                #pragma unroll
                for (int mt = 0; mt < 2; ++mt) {
                    mma16816(acc[mt][nt], ah[mt], bh0, bh1);
                    mma16816(acc[mt][nt], ah[mt], bm0, bm1);
                    mma16816(acc[mt][nt], am[mt], bh0, bh1);
                }
            }
        }

        // ---- softmax + gate (register/quad-shuffle only) ----
        float gg[2][2], riv[2][2];
        #pragma unroll
        for (int mt = 0; mt < 2; ++mt) {
            #pragma unroll
            for (int rh = 0; rh < 2; ++rh) {
                float mx = acc[mt][0][rh * 2];
                #pragma unroll
                for (int nt = 0; nt < 8; ++nt) {
                    mx = fmaxf(mx, acc[mt][nt][rh * 2]);
                    mx = fmaxf(mx, acc[mt][nt][rh * 2 + 1]);
                }
                mx = fmaxf(mx, __shfl_xor_sync(0xffffffffu, mx, 1));
                mx = fmaxf(mx, __shfl_xor_sync(0xffffffffu, mx, 2));
                float s = 0.f;
                #pragma unroll
                for (int nt = 0; nt < 8; ++nt) {
                    float e0 = __expf(acc[mt][nt][rh * 2]     - mx);
                    float e1 = __expf(acc[mt][nt][rh * 2 + 1] - mx);
                    acc[mt][nt][rh * 2]     = e0;
                    acc[mt][nt][rh * 2 + 1] = e1;
                    s += e0 + e1;
                }
                s += __shfl_xor_sync(0xffffffffu, s, 1);
                s += __shfl_xor_sync(0xffffffffu, s, 2);
                riv[mt][rh] = 1.0f / s;
                float gv = acc[mt][8][rh * 2];            // sim col 64 (q==0 lane)
                gv = __shfl_sync(0xffffffffu, gv, lane & ~3);
                gg[mt][rh] = 1.0f / (1.0f + __expf(-(gv + gbias)));
            }
        }

        // ---- repack P accumulators into GEMM2 A fragments (hi/mid) ----
        uint32_t aPh[2][4][4], aPm[2][4][4];
        #pragma unroll
        for (int mt = 0; mt < 2; ++mt) {
            #pragma unroll
            for (int kt = 0; kt < 4; ++kt) {
                splitpk(acc[mt][2*kt][0],   acc[mt][2*kt][1],   aPh[mt][kt][0], aPm[mt][kt][0]);
                splitpk(acc[mt][2*kt][2],   acc[mt][2*kt][3],   aPh[mt][kt][1], aPm[mt][kt][1]);
                splitpk(acc[mt][2*kt+1][0], acc[mt][2*kt+1][1], aPh[mt][kt][2], aPm[mt][kt][2]);
                splitpk(acc[mt][2*kt+1][2], acc[mt][2*kt+1][3], aPh[mt][kt][3], aPm[mt][kt][3]);
            }
        }

        // ---- GEMM2 (read = P @ mem), B frags via ldmatrix.trans on B1 ----
        const int sB = ((lane >> 3) & 1) * 8 + (lane & 7);
        const int dB = (lane >> 4) * 8;
        #pragma unroll
        for (int half = 0; half < 2; ++half) {
            float acc2[2][8][4];
            #pragma unroll
            for (int mt = 0; mt < 2; ++mt)
                #pragma unroll
                for (int nt = 0; nt < 8; ++nt)
                    #pragma unroll
                    for (int j = 0; j < 4; ++j) acc2[mt][nt][j] = 0.f;

            #pragma unroll
            for (int kt = 0; kt < 4; ++kt) {
                #pragma unroll
                for (int np = 0; np < 4; ++np) {
                    int n0 = half * 64 + np * 16;
                    uint32_t bo = (uint32_t)((kt * 16 + sB) * B1_PITCH + (n0 + dB) * 2);
                    uint32_t bh[4], bm[4];
                    ldsm4t(bh, sb + B1Hoff + bo);
                    ldsm4t(bm, sb + B1Moff + bo);
                    #pragma unroll
                    for (int mt = 0; mt < 2; ++mt) {
                        mma16816(acc2[mt][np*2],   aPh[mt][kt], bh[0], bh[1]);
                        mma16816(acc2[mt][np*2],   aPh[mt][kt], bm[0], bm[1]);
                        mma16816(acc2[mt][np*2],   aPm[mt][kt], bh[0], bh[1]);
                        mma16816(acc2[mt][np*2+1], aPh[mt][kt], bh[2], bh[3]);
                        mma16816(acc2[mt][np*2+1], aPh[mt][kt], bm[2], bm[3]);
                        mma16816(acc2[mt][np*2+1], aPm[mt][kt], bh[2], bh[3]);
                    }
                }
            }

            // epilogue: out = x + g*(riv*read - x)
            #pragma unroll
            for (int mt = 0; mt < 2; ++mt) {
                #pragma unroll
                for (int rh = 0; rh < 2; ++rh) {
                    int row = w * 32 + mt * 16 + rh * 8 + gp;
                    int g = row0 + row;
                    if (g < n) {
                        const float G  = gg[mt][rh];
                        const float RI = riv[mt][rh];
                        #pragma unroll
                        for (int nt = 0; nt < 8; ++nt) {
                            int d0 = half * 64 + nt * 8 + 2 * q;
                            uint32_t xoff = row * 256 + (((d0 >> 3) ^ (row & 7)) << 4)
                                          + (d0 & 7) * 2;
                            float2 fh = ubf2(*(const uint32_t*)(smc + XH + xoff));
                            float2 fm = ubf2(*(const uint32_t*)(smc + XM + xoff));
                            float x0 = fh.x + fm.x, x1 = fh.y + fm.y;
                            float r0 = acc2[mt][nt][rh * 2]     * RI;
                            float r1 = acc2[mt][nt][rh * 2 + 1] * RI;
                            float2 o;
                            o.x = x0 + G * (r0 - x0);
                            o.y = x1 + G * (r1 - x1);
                            *reinterpret_cast<float2*>(out + (size_t)g * DIMS + d0) = o;
                        }
                    }
                }
            }
        }
        __syncthreads();   // xh/xm reused next tile
    }
}

extern "C" void kernel_launch(void* const* d_in, const int* in_sizes, int n_in,
                              void* d_out, int out_size)
{
    const float* x      = (const float*)d_in[0];
    const float* mem    = (const float*)d_in[1];
    const float* gate_w = (const float*)d_in[2];
    const float* gate_b = (const float*)d_in[3];
    float* out = (float*)d_out;

    int n = in_sizes[0] / DIMS;
    int ntiles = (n + TILE_R - 1) / TILE_R;

    cudaFuncSetAttribute(gated_memory_mma,
                         cudaFuncAttributeMaxDynamicSharedMemorySize, (int)SMEM_TOTAL);
    int grid = ntiles < 2 * NSM ? ntiles : 2 * NSM;
    gated_memory_mma<<<grid, NTH, SMEM_TOTAL>>>(x, mem, gate_w, gate_b, out, n, ntiles);
}

// round 14
// speedup vs baseline: 1.1921x; 1.1921x over previous
#include <cuda_runtime.h>
#include <cuda_bf16.h>
#include <stdint.h>

#define DIMS     128
#define MSLOTS   64
#define NTH      256
#define NSM      148

// ---------------- SMEM: only B1 (mem + gate row), hi/mid split ----------------
// [72 slots][272B pitch] bf16; pitch 272 = 17*16B -> conflict-free ldmatrix gather
#define B1Hoff  0u
#define B1Moff  19584u
#define B1_PITCH 272
#define SMEM_TOTAL 39168u

static __device__ __forceinline__ uint32_t smem_u32(const void* p) {
    uint32_t a;
    asm("{ .reg .u64 t; cvta.to.shared.u64 t, %1; cvt.u32.u64 %0, t; }" : "=r"(a) : "l"(p));
    return a;
}
static __device__ __forceinline__ void ldsm4t(uint32_t* r, uint32_t a) {
    asm volatile("ldmatrix.sync.aligned.m8n8.x4.trans.shared.b16 {%0,%1,%2,%3}, [%4];"
                 : "=r"(r[0]), "=r"(r[1]), "=r"(r[2]), "=r"(r[3]) : "r"(a));
}
static __device__ __forceinline__ void mma16816(float* d, const uint32_t* a,
                                                uint32_t b0, uint32_t b1) {
    asm volatile(
        "mma.sync.aligned.m16n8k16.row.col.f32.bf16.bf16.f32 "
        "{%0,%1,%2,%3}, {%4,%5,%6,%7}, {%8,%9}, {%0,%1,%2,%3};"
        : "+f"(d[0]), "+f"(d[1]), "+f"(d[2]), "+f"(d[3])
        : "r"(a[0]), "r"(a[1]), "r"(a[2]), "r"(a[3]), "r"(b0), "r"(b1));
}
static __device__ __forceinline__ uint32_t pk2bf(__nv_bfloat16 a, __nv_bfloat16 b) {
    __nv_bfloat162 t; t.x = a; t.y = b;
    return *reinterpret_cast<uint32_t*>(&t);
}
static __device__ __forceinline__ void splitpk(float a, float b,
                                               uint32_t& hi, uint32_t& mid) {
    __nv_bfloat16 ha = __float2bfloat16_rn(a);
    __nv_bfloat16 hb = __float2bfloat16_rn(b);
    hi  = pk2bf(ha, hb);
    mid = pk2bf(__float2bfloat16_rn(a - __bfloat162float(ha)),
                __float2bfloat16_rn(b - __bfloat162float(hb)));
}

__global__ void __launch_bounds__(NTH, 2)
gated_memory_mma(const float* __restrict__ x,
                 const float* __restrict__ mem,
                 const float* __restrict__ gate_w,
                 const float* __restrict__ gate_b,
                 float* __restrict__ out,
                 int n, int ngroups)
{
    extern __shared__ char smc[];
    const uint32_t sb = smem_u32(smc);
    const int tid  = threadIdx.x;
    const int lane = tid & 31;
    const int w    = tid >> 5;          // warp 0..7
    const int q    = lane & 3;
    const int gp   = lane >> 2;

    // ---- stage B1 (mem rows + gate row + zero pad), hi/mid split ----
    for (int i = tid; i < MSLOTS * DIMS; i += NTH) {
        int s = i >> 7, d = i & 127;
        float v = mem[i];
        __nv_bfloat16 h = __float2bfloat16_rn(v);
        __nv_bfloat16 m = __float2bfloat16_rn(v - __bfloat162float(h));
        *(__nv_bfloat16*)(smc + B1Hoff + s * B1_PITCH + d * 2) = h;
        *(__nv_bfloat16*)(smc + B1Moff + s * B1_PITCH + d * 2) = m;
    }
    if (tid < DIMS) {   // gate row = slot 64
        float v = gate_w[tid];
        __nv_bfloat16 h = __float2bfloat16_rn(v);
        __nv_bfloat16 m = __float2bfloat16_rn(v - __bfloat162float(h));
        *(__nv_bfloat16*)(smc + B1Hoff + 64 * B1_PITCH + tid * 2) = h;
        *(__nv_bfloat16*)(smc + B1Moff + 64 * B1_PITCH + tid * 2) = m;
    }
    for (int i = tid; i < 476; i += NTH) {   // zero slots 65..71
        *(uint32_t*)(smc + B1Hoff + 65 * B1_PITCH + i * 4) = 0u;
        *(uint32_t*)(smc + B1Moff + 65 * B1_PITCH + i * 4) = 0u;
    }
    const float gbias = gate_b[0];
    __syncthreads();   // only sync in the kernel

    // ---- warp-independent loop over 16-row groups ----
    const int gwid   = blockIdx.x * (NTH / 32) + w;
    const int stride = gridDim.x * (NTH / 32);

    for (int grp = gwid; grp < ngroups; grp += stride) {
        const int r0 = grp * 16 + gp;        // row for rh=0
        const int r1 = r0 + 8;               // row for rh=1
        const bool ok0 = r0 < n, ok1 = r1 < n;
        const float* px0 = x + (size_t)r0 * DIMS + 2 * q;
        const float* px1 = x + (size_t)r1 * DIMS + 2 * q;

        // ---- GEMM1: sim[16 x 72] = x @ [mem|gw]^T, A direct from gmem ----
        float acc[9][4];
        #pragma unroll
        for (int nt = 0; nt < 9; ++nt)
            #pragma unroll
            for (int j = 0; j < 4; ++j) acc[nt][j] = 0.f;

        #pragma unroll
        for (int kt = 0; kt < 8; ++kt) {
            float2 a00 = make_float2(0.f, 0.f), a01 = a00, a10 = a00, a11 = a00;
            if (ok0) {
                a00 = *(const float2*)(px0 + kt * 16);
                a01 = *(const float2*)(px0 + kt * 16 + 8);
            }
            if (ok1) {
                a10 = *(const float2*)(px1 + kt * 16);
                a11 = *(const float2*)(px1 + kt * 16 + 8);
            }
            uint32_t ah[4], am[4];
            splitpk(a00.x, a00.y, ah[0], am[0]);   // (row gp,   k 2q..)
            splitpk(a10.x, a10.y, ah[1], am[1]);   // (row gp+8, k 2q..)
            splitpk(a01.x, a01.y, ah[2], am[2]);   // (row gp,   k 2q+8..)
            splitpk(a11.x, a11.y, ah[3], am[3]);   // (row gp+8, k 2q+8..)

            #pragma unroll
            for (int nt = 0; nt < 9; ++nt) {
                uint32_t bo = B1Hoff + (nt * 8 + gp) * B1_PITCH + (kt * 16 + 2 * q) * 2;
                uint32_t bh0 = *(const uint32_t*)(smc + bo);
                uint32_t bh1 = *(const uint32_t*)(smc + bo + 16);
                uint32_t bm0 = *(const uint32_t*)(smc + bo + (B1Moff - B1Hoff));
                uint32_t bm1 = *(const uint32_t*)(smc + bo + (B1Moff - B1Hoff) + 16);
                mma16816(acc[nt], ah, bh0, bh1);
                mma16816(acc[nt], ah, bm0, bm1);
                mma16816(acc[nt], am, bh0, bh1);
            }
        }

        // ---- softmax + gate (register/quad-shuffle only) ----
        float gg[2], riv[2];
        #pragma unroll
        for (int rh = 0; rh < 2; ++rh) {
            float mx = acc[0][rh * 2];
            #pragma unroll
            for (int nt = 0; nt < 8; ++nt) {
                mx = fmaxf(mx, acc[nt][rh * 2]);
                mx = fmaxf(mx, acc[nt][rh * 2 + 1]);
            }
            mx = fmaxf(mx, __shfl_xor_sync(0xffffffffu, mx, 1));
            mx = fmaxf(mx, __shfl_xor_sync(0xffffffffu, mx, 2));
            float s = 0.f;
            #pragma unroll
            for (int nt = 0; nt < 8; ++nt) {
                float e0 = __expf(acc[nt][rh * 2]     - mx);
                float e1 = __expf(acc[nt][rh * 2 + 1] - mx);
                acc[nt][rh * 2]     = e0;
                acc[nt][rh * 2 + 1] = e1;
                s += e0 + e1;
            }
            s += __shfl_xor_sync(0xffffffffu, s, 1);
            s += __shfl_xor_sync(0xffffffffu, s, 2);
            riv[rh] = 1.0f / s;
            float gv = acc[8][rh * 2];                 // sim col 64 (q==0 lane)
            gv = __shfl_sync(0xffffffffu, gv, lane & ~3);
            gg[rh] = 1.0f / (1.0f + __expf(-(gv + gbias)));
        }

        // ---- repack P accumulators into GEMM2 A fragments (hi/mid) ----
        uint32_t aPh[4][4], aPm[4][4];
        #pragma unroll
        for (int kt = 0; kt < 4; ++kt) {
            splitpk(acc[2*kt][0],   acc[2*kt][1],   aPh[kt][0], aPm[kt][0]);
            splitpk(acc[2*kt][2],   acc[2*kt][3],   aPh[kt][1], aPm[kt][1]);
            splitpk(acc[2*kt+1][0], acc[2*kt+1][1], aPh[kt][2], aPm[kt][2]);
            splitpk(acc[2*kt+1][2], acc[2*kt+1][3], aPh[kt][3], aPm[kt][3]);
        }

        // ---- GEMM2 (read = P @ mem), B via ldmatrix.trans; x prefetched ----
        const int sB = ((lane >> 3) & 1) * 8 + (lane & 7);
        const int dB = (lane >> 4) * 8;
        #pragma unroll
        for (int half = 0; half < 2; ++half) {
            // prefetch epilogue x for this half (L2-hot); overlaps with MMAs below
            float2 xv0[8], xv1[8];
            #pragma unroll
            for (int nt = 0; nt < 8; ++nt) {
                int d0 = half * 64 + nt * 8;
                xv0[nt] = ok0 ? *(const float2*)(px0 + d0) : make_float2(0.f, 0.f);
                xv1[nt] = ok1 ? *(const float2*)(px1 + d0) : make_float2(0.f, 0.f);
            }

            float acc2[8][4];
            #pragma unroll
            for (int nt = 0; nt < 8; ++nt)
                #pragma unroll
                for (int j = 0; j < 4; ++j) acc2[nt][j] = 0.f;

            #pragma unroll
            for (int kt = 0; kt < 4; ++kt) {
                #pragma unroll
                for (int np = 0; np < 4; ++np) {
                    int n0 = half * 64 + np * 16;
                    uint32_t bo = (uint32_t)((kt * 16 + sB) * B1_PITCH + (n0 + dB) * 2);
                    uint32_t bh[4], bm[4];
                    ldsm4t(bh, sb + B1Hoff + bo);
                    ldsm4t(bm, sb + B1Moff + bo);
                    mma16816(acc2[np*2],   aPh[kt], bh[0], bh[1]);
                    mma16816(acc2[np*2],   aPh[kt], bm[0], bm[1]);
                    mma16816(acc2[np*2],   aPm[kt], bh[0], bh[1]);
                    mma16816(acc2[np*2+1], aPh[kt], bh[2], bh[3]);
                    mma16816(acc2[np*2+1], aPh[kt], bm[2], bm[3]);
                    mma16816(acc2[np*2+1], aPm[kt], bh[2], bh[3]);
                }
            }

            // epilogue: out = x + g*(riv*read - x)
            #pragma unroll
            for (int rh = 0; rh < 2; ++rh) {
                int row = (rh == 0) ? r0 : r1;
                if (row < n) {
                    const float G  = gg[rh];
                    const float RI = riv[rh];
                    #pragma unroll
                    for (int nt = 0; nt < 8; ++nt) {
                        float2 xv = (rh == 0) ? xv0[nt] : xv1[nt];
                        float rd0 = acc2[nt][rh * 2]     * RI;
                        float rd1 = acc2[nt][rh * 2 + 1] * RI;
                        float2 o;
                        o.x = xv.x + G * (rd0 - xv.x);
                        o.y = xv.y + G * (rd1 - xv.y);
                        int d0 = half * 64 + nt * 8 + 2 * q;
                        *reinterpret_cast<float2*>(out + (size_t)row * DIMS + d0) = o;
                    }
                }
            }
        }
    }
}

extern "C" void kernel_launch(void* const* d_in, const int* in_sizes, int n_in,
                              void* d_out, int out_size)
{
    const float* x      = (const float*)d_in[0];
    const float* mem    = (const float*)d_in[1];
    const float* gate_w = (const float*)d_in[2];
    const float* gate_b = (const float*)d_in[3];
    float* out = (float*)d_out;

    int n = in_sizes[0] / DIMS;
    int ngroups = (n + 15) / 16;

    cudaFuncSetAttribute(gated_memory_mma,
                         cudaFuncAttributeMaxDynamicSharedMemorySize, (int)SMEM_TOTAL);
    int grid = 2 * NSM;
    int maxgrid = (ngroups + (NTH / 32) - 1) / (NTH / 32);
    if (grid > maxgrid) grid = maxgrid;
    gated_memory_mma<<<grid, NTH, SMEM_TOTAL>>>(x, mem, gate_w, gate_b, out, n, ngroups);
}